// round 12
// baseline (speedup 1.0000x reference)
#include <cuda_runtime.h>
#include <stdint.h>

// ---------------------------------------------------------------------------
// BboxSegEnsembler: seg gather fused block-wise with topk/NMS detection chain
// Output layout (float32): [ seg (2*192^3) | dets (100,8) | labels (100) ]
//   out_size = 14,156,676 = 2*192^3 + 800 + 100  (verified identity)
// ---------------------------------------------------------------------------

#define IMGD   192
#define IMGV   (192*192*192)
#define NPROP  200000
#define KPRE   1000
#define MAXPER 100
#define CAND_CAP 4096
#define NWORDS 16
#define SEG_BLOCKS 1728        // (192*192*48) / 1024 exactly

typedef unsigned long long u64;

// ---------------- device scratch (no allocation allowed) -------------------
__device__ unsigned int g_hist[65536];
__device__ unsigned int g_candCount;
__device__ unsigned int g_pivot;
__device__ u64          g_key[NPROP];
__device__ u64          g_cand[CAND_CAP];
__device__ u64          g_merge[2048];
__device__ float        g_bo[KPRE * 6];
__device__ float        g_boxOut[KPRE * 6];
__device__ float        g_vol[KPRE];
__device__ float        g_score[KPRE];
__device__ int          g_lab[KPRE];
__device__ u64          g_validw[NWORDS];
__device__ u64          g_mask[16384];       // rows 1000..1023 never written (stay 0)

__device__ __forceinline__ unsigned key32(float f) {
    unsigned u = __float_as_uint(f);
    return (u & 0x80000000u) ? ~u : (u | 0x80000000u);
}

// ---------------- seg gather slice (1024-thread block granularity) ----------
// scan overwrite semantics -> last-writer gather:
//   origin per axis: v<48 -> 0 ; v<96 -> 48 ; else 96
//   coverage 2 iff 48<=v<144 (second covering origin = last-48)
__device__ __forceinline__ void seg_slice(
    int sb, const float* __restrict__ tiles, const float* __restrict__ w,
    float* __restrict__ out)
{
    int qid = sb * 1024 + (int)threadIdx.x;   // < 192*192*48 by construction
    int zq = qid % 48;
    int z  = zq * 4;
    int r  = qid / 48;
    int y  = r % IMGD;
    int x  = r / IMGD;

    int ox = (x < 48) ? 0 : ((x < 96) ? 48 : 96);
    int oy = (y < 48) ? 0 : ((y < 96) ? 48 : 96);
    int oz = (z < 48) ? 0 : ((z < 96) ? 48 : 96);
    int nx = (x >= 48 && x < 144) ? 2 : 1;
    int ny = (y >= 48 && y < 144) ? 2 : 1;
    int nz = (z >= 48 && z < 144) ? 2 : 1;

    float4 cnt = make_float4(0.f, 0.f, 0.f, 0.f);
    for (int a = 0; a < nx; a++) {
        int lx = x - ox + a * 48;
        for (int b = 0; b < ny; b++) {
            int ly = y - oy + b * 48;
            int base = lx * 9216 + ly * 96;
            for (int c = 0; c < nz; c++) {
                int lz = z - oz + c * 48;
                float4 wv = *(const float4*)(w + base + lz);
                cnt.x += wv.x; cnt.y += wv.y; cnt.z += wv.z; cnt.w += wv.w;
            }
        }
    }

    int widx = (x - ox) * 9216 + (y - oy) * 96 + (z - oz);
    float4 wl = *(const float4*)(w + widx);
    float4 rr;
    rr.x = __fdividef(wl.x, cnt.x);
    rr.y = __fdividef(wl.y, cnt.y);
    rr.z = __fdividef(wl.z, cnt.z);
    rr.w = __fdividef(wl.w, cnt.w);

    int ti = (ox / 48) * 9 + (oy / 48) * 3 + (oz / 48);
    int tbase = ti * 2 * 884736 + widx;
    float4 t0 = *(const float4*)(tiles + tbase);
    float4 t1 = *(const float4*)(tiles + tbase + 884736);

    int oidx = x * 36864 + y * IMGD + z;
    *(float4*)(out + oidx)        = make_float4(t0.x*rr.x, t0.y*rr.y, t0.z*rr.z, t0.w*rr.w);
    *(float4*)(out + oidx + IMGV) = make_float4(t1.x*rr.x, t1.y*rr.y, t1.z*rr.z, t1.w*rr.w);
}

// ---------------- K1: key pack + 16-bit-bucket histogram (+seg) -------------
__global__ __launch_bounds__(1024) void k1_hist(
    const float* __restrict__ bb, const float* __restrict__ tiles,
    const float* __restrict__ w, float* __restrict__ out, int segBase)
{
    if (blockIdx.x < 200) {
        int gid = blockIdx.x * 1024 + threadIdx.x;
        if (gid < NPROP) {
            unsigned k = key32(bb[gid * 7 + 6]);
            g_key[gid] = ((u64)k << 32) | (unsigned)(~gid);   // ~i: lower idx wins ties
            atomicAdd(&g_hist[k >> 16], 1u);
        }
    } else {
        seg_slice(segBase + (int)blockIdx.x - 200, tiles, w, out);
    }
}

// ---------------- K2: pivot bucket select + counter resets (+seg) -----------
__global__ __launch_bounds__(1024) void k2_pivot(
    const float* __restrict__ tiles, const float* __restrict__ w,
    float* __restrict__ out, int segBase)
{
    if (blockIdx.x == 0) {
        __shared__ unsigned part[1024];
        int t = threadIdx.x;
        if (t == 0) g_candCount = 0;
        if (t < NWORDS) g_validw[t] = 0ULL;
        unsigned s = 0;
        #pragma unroll 8
        for (int e = 0; e < 64; e++) s += g_hist[t * 64 + e];
        part[t] = s;
        __syncthreads();
        for (int off = 1; off < 1024; off <<= 1) {     // suffix sum
            unsigned v = (t + off < 1024) ? part[t + off] : 0u;
            __syncthreads();
            part[t] += v;
            __syncthreads();
        }
        unsigned mine = part[t];
        unsigned nxt  = (t == 1023) ? 0u : part[t + 1];
        if (mine >= KPRE && nxt < KPRE) {
            unsigned acc = nxt;
            int p = t * 64;
            for (int b = 63; b >= 0; b--) {
                acc += g_hist[t * 64 + b];
                if (acc >= KPRE) { p = t * 64 + b; break; }
            }
            g_pivot = (unsigned)p;   // #{keys in buckets >= p} >= KPRE
        }
    } else {
        seg_slice(segBase + (int)blockIdx.x - 1, tiles, w, out);
    }
}

// ---------------- K3: collect candidates + re-zero hist for replay (+seg) ---
__global__ __launch_bounds__(1024) void k3_collect(
    const float* __restrict__ tiles, const float* __restrict__ w,
    float* __restrict__ out, int segBase)
{
    if (blockIdx.x < 200) {
        int gid = blockIdx.x * 1024 + threadIdx.x;
        if (gid < 65536) g_hist[gid] = 0;          // idempotence across graph replays
        if (gid < NPROP) {
            u64 kk = g_key[gid];
            if ((unsigned)(kk >> 48) >= g_pivot) {
                unsigned pos = atomicAdd(&g_candCount, 1u);
                if (pos < CAND_CAP) g_cand[pos] = kk;
            }
        }
    } else {
        seg_slice(segBase + (int)blockIdx.x - 200, tiles, w, out);
    }
}

// ---------------- K4: 4x 1024-elem bitonic sorts, descending (+seg) ---------
__global__ __launch_bounds__(1024) void k4_sort(
    const float* __restrict__ tiles, const float* __restrict__ w,
    float* __restrict__ out, int segBase)
{
    if (blockIdx.x < 4) {
        __shared__ u64 s[1024];
        int t = threadIdx.x;
        unsigned cc = g_candCount; if (cc > CAND_CAP) cc = CAND_CAP;
        int base = blockIdx.x * 1024;
        s[t] = (base + t < (int)cc) ? g_cand[base + t] : 0ULL;
        __syncthreads();
        for (int k = 2; k <= 1024; k <<= 1) {
            for (int j = k >> 1; j > 0; j >>= 1) {
                int exj = t ^ j;
                if (exj > t) {
                    u64 a = s[t], b = s[exj];
                    bool desc = ((t & k) == 0);
                    if (desc ? (a < b) : (a > b)) { s[t] = b; s[exj] = a; }
                }
                __syncthreads();
            }
        }
        g_cand[base + t] = s[t];
    } else {
        seg_slice(segBase + (int)blockIdx.x - 4, tiles, w, out);
    }
}

// ---------------- K5: merge sorted pairs (0,1)->merge[0:1024), (2,3)->rest --
__global__ __launch_bounds__(1024) void k5_mergeA(
    const float* __restrict__ tiles, const float* __restrict__ w,
    float* __restrict__ out, int segBase)
{
    if (blockIdx.x < 2) {
        __shared__ u64 s[2048];
        int t = threadIdx.x, base = blockIdx.x * 2048;
        s[t]        = g_cand[base + t];            // sorted desc
        s[1024 + t] = g_cand[base + 2047 - t];     // reversed -> bitonic whole
        __syncthreads();
        for (int j = 1024; j > 0; j >>= 1) {
            #pragma unroll
            for (int h = 0; h < 2; h++) {
                int e = t + h * 1024;
                int exj = e ^ j;
                if (exj > e) {
                    u64 a = s[e], b = s[exj];
                    if (a < b) { s[e] = b; s[exj] = a; }   // descending merge
                }
            }
            __syncthreads();
        }
        g_merge[blockIdx.x * 1024 + t] = s[t];     // top-1024 of the pair
    } else {
        seg_slice(segBase + (int)blockIdx.x - 2, tiles, w, out);
    }
}

// ---------------- K6: final merge -> exact top-1000 + fused box prep (+seg) -
__global__ __launch_bounds__(1024) void k6_mergeB_prep(
    const float* __restrict__ bb, const int* __restrict__ labels,
    const float* __restrict__ tiles, const float* __restrict__ w,
    float* __restrict__ out, int segBase)
{
    if (blockIdx.x == 0) {
        __shared__ u64 s[2048];
        int t = threadIdx.x;
        s[t]        = g_merge[t];
        s[1024 + t] = g_merge[2047 - t];
        __syncthreads();
        for (int j = 1024; j > 0; j >>= 1) {
            #pragma unroll
            for (int h = 0; h < 2; h++) {
                int e = t + h * 1024;
                int exj = e ^ j;
                if (exj > e) {
                    u64 a = s[e], b = s[exj];
                    if (a < b) { s[e] = b; s[exj] = a; }
                }
            }
            __syncthreads();
        }
        int r = t;
        if (r < KPRE) {
            int i = (int)(~(unsigned)(s[r] & 0xFFFFFFFFu));
            float p[6];
            #pragma unroll
            for (int d = 0; d < 6; d++)
                p[d] = fminf(fmaxf(bb[i * 7 + d], 0.0f), 192.0f);
            float sc = bb[i * 7 + 6];
            bool valid = (sc > 0.01f)
                       && (p[3] - p[0] >= 0.01f)
                       && (p[4] - p[1] >= 0.01f)
                       && (p[5] - p[2] >= 0.01f);
            int lab = labels[i];
            float off = (float)lab * 384.0f;       // CLASS_OFFSET = 2*192
            float bo[6];
            #pragma unroll
            for (int d = 0; d < 6; d++) {
                bo[d] = p[d] + off;
                g_bo[r * 6 + d] = bo[d];
                g_boxOut[r * 6 + d] = p[d];
            }
            g_vol[r]   = ((bo[3] - bo[0]) * (bo[4] - bo[1])) * (bo[5] - bo[2]);
            g_score[r] = sc;
            g_lab[r]   = lab;
            if (valid) atomicOr(&g_validw[r >> 6], 1ULL << (r & 63));
        }
    } else {
        seg_slice(segBase + (int)blockIdx.x - 1, tiles, w, out);
    }
}

// ---------------- K7: IoU>thr suppression bitmask (+seg) --------------------
// Lanes in a warp share the column word (broadcast LDS); stride-7 rows are
// coprime with 32 banks -> conflict-free.
__global__ __launch_bounds__(1024) void k7_mask(
    const float* __restrict__ tiles, const float* __restrict__ w,
    float* __restrict__ out, int segBase)
{
    if (blockIdx.x < 16) {
        __shared__ float sbox[KPRE][7];            // 28KB
        int t = threadIdx.x;
        for (int e = t; e < KPRE; e += 1024) {
            #pragma unroll
            for (int d = 0; d < 6; d++) sbox[e][d] = g_bo[e * 6 + d];
            sbox[e][6] = g_vol[e];
        }
        __syncthreads();
        int li = t & 63;                           // row within 64-row group
        int cg = t >> 6;                           // column word (warp-uniform)
        int i  = blockIdx.x * 64 + li;
        if (i < KPRE) {
            float m0 = sbox[i][0], m1 = sbox[i][1], m2 = sbox[i][2];
            float M0 = sbox[i][3], M1 = sbox[i][4], M2 = sbox[i][5];
            float vi = sbox[i][6];
            u64 bits = 0ULL;
            int j0 = cg * 64;
            int jmax = KPRE - j0; if (jmax > 64) jmax = 64;
            for (int jj = 0; jj < jmax; jj++) {
                const float* B = sbox[j0 + jj];
                float i0 = fmaxf(fminf(M0, B[3]) - fmaxf(m0, B[0]), 0.0f);
                float i1 = fmaxf(fminf(M1, B[4]) - fmaxf(m1, B[1]), 0.0f);
                float i2 = fmaxf(fminf(M2, B[5]) - fmaxf(m2, B[2]), 0.0f);
                float inter = (i0 * i1) * i2;
                float uni = vi + B[6] - inter;
                float iou = inter / fmaxf(uni, 1e-6f);   // IEEE div matches ref
                if (iou > 0.1f) bits |= (1ULL << jj);
            }
            g_mask[i * NWORDS + cg] = bits;
        }
    } else {
        seg_slice(segBase + (int)blockIdx.x - 16, tiles, w, out);
    }
}

// ---------------- K8: sequential NMS, staged per 64-row block, early exit ---
__global__ __launch_bounds__(1024) void k8_nms(
    const float* __restrict__ tiles, const float* __restrict__ w,
    float* __restrict__ out, float* __restrict__ outDet,
    float* __restrict__ outLab, int segBase)
{
    if (blockIdx.x == 0) {
        __shared__ u64 sm[1024];                   // 64 rows x 16 words (8KB)
        __shared__ int s_fidx[MAXPER];
        __shared__ int s_nk;
        __shared__ int s_done;
        int t = threadIdx.x;
        if (t == 0) { s_nk = 0; s_done = 0; }
        u64 remv = 0ULL;                           // lane L<16 owns suppression word L
        int nk = 0;
        __syncthreads();

        for (int b = 0; b < NWORDS; b++) {
            sm[t] = g_mask[b * 1024 + t];          // rows [b*64, b*64+64)
            __syncthreads();
            if (t < 32) {
                int lane = t;
                u64 alive = g_validw[b] & ~__shfl_sync(0xFFFFFFFFu, remv, b);
                while (alive && nk < MAXPER) {
                    int il = __ffsll((long long)alive) - 1;   // lowest surviving row
                    if (lane == 0) s_fidx[nk] = b * 64 + il;
                    nk++;
                    u64 rowL = (lane < NWORDS) ? sm[il * 16 + lane] : 0ULL;
                    remv |= rowL;
                    u64 rowb = sm[il * 16 + b];    // broadcast LDS
                    alive &= ~rowb;
                    alive &= ~(1ULL << il);
                }
                if (lane == 0 && (nk >= MAXPER || b == NWORDS - 1)) {
                    s_nk = nk;
                    s_done = (nk >= MAXPER) ? 1 : 0;
                }
            }
            __syncthreads();
            if (s_done) break;
        }

        int nkf = s_nk;
        // dets (100,8) = [6 coords | score | score]; zeros for empty slots
        for (int e = t; e < MAXPER * 8; e += 1024) {
            int sidx = e >> 3, c = e & 7;
            float v = 0.0f;
            if (sidx < nkf) {
                int r = s_fidx[sidx];
                v = (c < 6) ? g_boxOut[r * 6 + c] : g_score[r];
            }
            outDet[e] = v;
        }
        for (int sidx = t; sidx < MAXPER; sidx += 1024)
            outLab[sidx] = (sidx < nkf) ? (float)g_lab[s_fidx[sidx]] : -1.0f;
    } else {
        seg_slice(segBase + (int)blockIdx.x - 1, tiles, w, out);
    }
}

// ---------------------------------------------------------------------------
extern "C" void kernel_launch(void* const* d_in, const int* in_sizes, int n_in,
                              void* d_out, int out_size) {
    const float* tiles  = (const float*)d_in[0];   // seg_tiles (27,1,2,96,96,96)
    const float* w      = (const float*)d_in[1];   // tile_weight (96,96,96)
    const float* bb     = (const float*)d_in[2];   // bboxes_raw (N,7)
    const int*   labels = (const int*)d_in[3];     // labels_raw (N,) int32
    // d_in[4] = tile_origins: fixed {0,48,96}^3 meshgrid, handled analytically
    float* out    = (float*)d_out;
    float* outDet = out + 2 * IMGV;
    float* outLab = outDet + MAXPER * 8;

    // seg slices proportional to estimated det stage cost (sum = 1728):
    // det est (us):  k1 1.5  k2 0.5  k3 1.0  k4 3.0  k5 1.5  k6 1.5  k7 2.0  k8 2.0
    // slices:        199     66      133     399     199     199     266     267
    // bases:         0       199     265     398     797     996     1195    1461
    k1_hist       <<<200 + 199, 1024>>>(bb, tiles, w, out, 0);
    k2_pivot      <<<1   + 66,  1024>>>(tiles, w, out, 199);
    k3_collect    <<<200 + 133, 1024>>>(tiles, w, out, 265);
    k4_sort       <<<4   + 399, 1024>>>(tiles, w, out, 398);
    k5_mergeA     <<<2   + 199, 1024>>>(tiles, w, out, 797);
    k6_mergeB_prep<<<1   + 199, 1024>>>(bb, labels, tiles, w, out, 996);
    k7_mask       <<<16  + 266, 1024>>>(tiles, w, out, 1195);
    k8_nms        <<<1   + 267, 1024>>>(tiles, w, out, outDet, outLab, 1461);
}